// round 10
// baseline (speedup 1.0000x reference)
#include <cuda_runtime.h>
#include <cstdint>

// Attention_41480794145302 — mma.sync tf32, frag-packed smem, wide tiles,
// double-buffered pipelined loads, shuffle-transpose attention (no P smem).
// x:[B,512,L]  w_qkv:[1536,512]  w_out:[512,512]  b_out:[512]  out:[B,512,L]
// B=4, L=2048, H=8, DH=64

namespace {
constexpr int Bn  = 4;
constexpr int DIM = 512;
constexpr int Ln  = 2048;
constexpr int Hn  = 8;
constexpr int DH  = 64;
constexpr int HID = 512;
constexpr float SCALE = 0.125f;   // 64^-0.5
}

// scratch (allocation-free rule: __device__ globals)
__device__ float g_q[Bn * Hn * Ln * DH];  // [b,h,l,c]
__device__ float g_k[Bn * Hn * Ln * DH];  // [b,h,l,c]
__device__ float g_v[Bn * Hn * Ln * DH];  // [b,h,l,c]
__device__ float g_o[Bn * HID * Ln];      // [b, h*64+c, l]

__device__ __forceinline__ float tf32r(float f) {   // round-to-nearest tf32
    uint32_t u;
    asm("cvt.rna.tf32.f32 %0, %1;" : "=r"(u) : "f"(f));
    return __uint_as_float(u);
}
__device__ __forceinline__ uint32_t fbits(float f) { return __float_as_uint(f); }

// D += A(16x8,row) * B(8x8,col)  tf32
__device__ __forceinline__ void mma8(float* c, const uint32_t* a, const uint32_t* b) {
    asm volatile(
        "mma.sync.aligned.m16n8k8.row.col.f32.tf32.tf32.f32 "
        "{%0,%1,%2,%3}, {%4,%5,%6,%7}, {%8,%9}, {%0,%1,%2,%3};"
        : "+f"(c[0]), "+f"(c[1]), "+f"(c[2]), "+f"(c[3])
        : "r"(a[0]), "r"(a[1]), "r"(a[2]), "r"(a[3]), "r"(b[0]), "r"(b[1]));
}

// ---------------------------------------------------------------------------
// Fragment-packed smem layouts (validated R6 scheme).
// A region = one 16(M)x8(K) fragment tile: 132 floats; one LDS.128 per frag.
// B region = one 8(K)x8(N) fragment tile: 66 floats; one LDS.64 per frag.
// ---------------------------------------------------------------------------
__device__ __forceinline__ int a_idx(int region, int rr, int kk) {
    const int g = rr & 7;
    const int lane = (g * 4 + (kk & 3)) ^ ((g >> 1) & 3);
    return region * 132 + lane * 4 + (rr >> 3) + 2 * (kk >> 2);
}
__device__ __forceinline__ void a_frag(uint32_t* a, const float* base, int region,
                                       int g, int tig) {
    const float4 f = *(const float4*)&base[region * 132 + (((g * 4 + tig) ^ ((g >> 1) & 3)) * 4)];
    a[0] = fbits(f.x); a[1] = fbits(f.y); a[2] = fbits(f.z); a[3] = fbits(f.w);
}
__device__ __forceinline__ int b_idx(int region, int kk, int nn) {
    const int m = (region ^ (region >> 3)) & 3;
    return region * 66 + (((nn * 4 + (kk & 3)) ^ m) * 2) + (kk >> 2);
}
__device__ __forceinline__ void b_frag(uint32_t* b, const float* base, int region,
                                       int g, int tig) {
    const int m = (region ^ (region >> 3)) & 3;
    const float2 f = *(const float2*)&base[region * 66 + (((g * 4 + tig) ^ m) * 2)];
    b[0] = fbits(f.x); b[1] = fbits(f.y);
}

// ---------------------------------------------------------------------------
// Kernel 1: QKV projection.  C[1536,2048] = w_qkv[1536,512] @ x_b[512,2048]
// Block tile 128(M) x 128(N), K-chunk 32, 8 warps; warp tile 32x64.
// Double-buffered smem, 1 sync per chunk, pipelined global loads.
// ---------------------------------------------------------------------------
namespace {
constexpr int NWP = 32 * 132;   // one W chunk A-pack
constexpr int NXP = 64 * 66;    // one X chunk B-pack
constexpr int GEMM_SMEM = (2 * NWP + 2 * NXP) * 4;   // 67584 B
}

__global__ __launch_bounds__(256, 2) void qkv_mma(const float* __restrict__ x,
                                                  const float* __restrict__ w) {
    extern __shared__ float dsm[];
    const int t    = threadIdx.x;
    const int w8   = t >> 5;
    const int lane = t & 31;
    const int g    = lane >> 2;
    const int tig  = lane & 3;
    const int wm   = w8 & 3;          // M sub-tile (32 rows)
    const int wn   = w8 >> 2;         // N sub-tile (64 cols)
    const int ltile = blockIdx.x * 128;
    const int bm    = blockIdx.y;     // 0..11
    const int b     = blockIdx.z;

    const float* xb = x + (size_t)b * DIM * Ln;

    // per-thread load coords
    const int wr = t >> 3;            // W row (of 128 via jj)
    const int wc = (t & 7) * 4;       // W k-col
    const int xr = t >> 5;            // X k-row (of 32 via jj)
    const int xc = (t & 31) * 4;      // X l-col

    float4 wv[4], xv[4];
    #pragma unroll
    for (int jj = 0; jj < 4; jj++) {
        wv[jj] = *(const float4*)&w[(size_t)(bm * 128 + jj * 32 + wr) * DIM + wc];
        xv[jj] = *(const float4*)&xb[(size_t)(jj * 8 + xr) * Ln + ltile + xc];
    }

    float acc[16][4] = {};            // [mt*8+nt][reg]

    for (int ci = 0; ci < DIM / 32; ci++) {
        float* WsP = dsm + (ci & 1) * NWP;
        float* XsP = dsm + 2 * NWP + (ci & 1) * NXP;

        // pack stores from prefetched regs
        #pragma unroll
        for (int jj = 0; jj < 4; jj++) {
            const int r = jj * 32 + wr;
            const int region = (r >> 4) * 4 + (wc >> 3);
            const int rr = r & 15;
            const int kb = wc & 7;
            const float4 v = wv[jj];
            WsP[a_idx(region, rr, kb + 0)] = tf32r(v.x);
            WsP[a_idx(region, rr, kb + 1)] = tf32r(v.y);
            WsP[a_idx(region, rr, kb + 2)] = tf32r(v.z);
            WsP[a_idx(region, rr, kb + 3)] = tf32r(v.w);
        }
        #pragma unroll
        for (int jj = 0; jj < 4; jj++) {
            const int r = jj * 8 + xr;
            const int region = (r >> 3) * 16 + (xc >> 3);
            const int kk = r & 7;
            const int nb = xc & 7;
            const float4 v = xv[jj];
            XsP[b_idx(region, kk, nb + 0)] = tf32r(v.x);
            XsP[b_idx(region, kk, nb + 1)] = tf32r(v.y);
            XsP[b_idx(region, kk, nb + 2)] = tf32r(v.z);
            XsP[b_idx(region, kk, nb + 3)] = tf32r(v.w);
        }
        __syncthreads();

        if (ci + 1 < DIM / 32) {      // pipelined loads for next chunk
            const int kc = (ci + 1) * 32;
            #pragma unroll
            for (int jj = 0; jj < 4; jj++) {
                wv[jj] = *(const float4*)&w[(size_t)(bm * 128 + jj * 32 + wr) * DIM + kc + wc];
                xv[jj] = *(const float4*)&xb[(size_t)(kc + jj * 8 + xr) * Ln + ltile + xc];
            }
        }

        #pragma unroll
        for (int ks = 0; ks < 4; ks++) {
            uint32_t a[2][4];
            a_frag(a[0], WsP, (wm * 2 + 0) * 4 + ks, g, tig);
            a_frag(a[1], WsP, (wm * 2 + 1) * 4 + ks, g, tig);
            #pragma unroll
            for (int nt = 0; nt < 8; nt++) {
                uint32_t bf[2];
                b_frag(bf, XsP, ks * 16 + wn * 8 + nt, g, tig);
                mma8(acc[nt], a[0], bf);
                mma8(acc[8 + nt], a[1], bf);
            }
        }
    }

    // epilogue: scatter into heads layout
    #pragma unroll
    for (int mt = 0; mt < 2; mt++) {
        #pragma unroll
        for (int nt = 0; nt < 8; nt++) {
            #pragma unroll
            for (int reg = 0; reg < 4; reg++) {
                const int m = bm * 128 + wm * 32 + mt * 16 + g + ((reg >= 2) ? 8 : 0);
                const int l = ltile + wn * 64 + nt * 8 + tig * 2 + (reg & 1);
                const int tile = m >> 6;
                const int sec  = tile >> 3;       // 0=q 1=k 2=v
                const int h    = tile & 7;
                const int c    = m & 63;
                float val = acc[mt * 8 + nt][reg];
                if (sec == 0) val *= SCALE;
                float* dst = (sec == 0) ? g_q : ((sec == 1) ? g_k : g_v);
                dst[((size_t)(b * Hn + h) * Ln + l) * DH + c] = val;
            }
        }
    }
}

// ---------------------------------------------------------------------------
// Kernel 2: flash attention.  Block = 128 q-rows; KV tiles of 64; 8 warps,
// warp tile 16 rows x 64 keys.  P stays in registers: MMA2 A-operand built
// by in-warp shuffle transpose.  1 __syncthreads per KV iteration.
// Double-buffered K/V, pipelined LDG.  Row-sums fully warp-local.
// ---------------------------------------------------------------------------
namespace {
constexpr int NQP = 64 * 132;   // Q A-pack: 8 mtiles x 8 ktiles
constexpr int NKP = 64 * 66;    // K B-pack: 8 ktiles(c) x 8 ntiles(key)
constexpr int NVP = 64 * 66;    // V B-pack: 8 ktiles(key) x 8 ntiles(c)
constexpr int OFF_QP = 0;
constexpr int OFF_KP = OFF_QP + NQP;
constexpr int OFF_VP = OFF_KP + 2 * NKP;
constexpr int ATTN_SMEM = (OFF_VP + 2 * NVP) * 4;   // 101376 B
}

__global__ __launch_bounds__(256, 2) void attn_mma() {
    extern __shared__ float sm[];
    float* QP = sm + OFF_QP;

    const int t    = threadIdx.x;
    const int w8   = t >> 5;
    const int lane = t & 31;
    const int g    = lane >> 2;
    const int tig  = lane & 3;
    const int wm   = w8;              // 16-row slice per warp
    const int bh   = blockIdx.y;
    const int lq0  = blockIdx.x * 128;

    const float* qb = g_q + (size_t)bh * Ln * DH;
    const float* kb = g_k + (size_t)bh * Ln * DH;
    const float* vb = g_v + (size_t)bh * Ln * DH;

    // load Q tile (once): 128 x 64 -> A-pack
    #pragma unroll
    for (int jj = 0; jj < 8; jj++) {
        const int pos = t + 256 * jj;
        const int r   = pos >> 4;
        const int c4  = (pos & 15) * 4;
        const float4 v = *(const float4*)&qb[(size_t)(lq0 + r) * DH + c4];
        const int region = (r >> 4) * 8 + (c4 >> 3);
        const int rr = r & 15;
        const int kb2 = c4 & 7;
        QP[a_idx(region, rr, kb2 + 0)] = tf32r(v.x);
        QP[a_idx(region, rr, kb2 + 1)] = tf32r(v.y);
        QP[a_idx(region, rr, kb2 + 2)] = tf32r(v.z);
        QP[a_idx(region, rr, kb2 + 3)] = tf32r(v.w);
    }

    // per-thread KV load coords: row 0..63, 16 consecutive c cols
    const int krow  = t >> 2;
    const int kcol0 = (t & 3) * 16;

    // prefetch KV tile 0
    float4 kvr[4], vvr[4];
    #pragma unroll
    for (int q4 = 0; q4 < 4; q4++) {
        kvr[q4] = *(const float4*)&kb[(size_t)krow * DH + kcol0 + q4 * 4];
        vvr[q4] = *(const float4*)&vb[(size_t)krow * DH + kcol0 + q4 * 4];
    }

    float oacc[8][4] = {};            // [nt2][reg]
    float ps_tot[2] = {0.0f, 0.0f};   // row-sum accumulators (rows g, g+8)

    const int s0l = (lane & ~3) + (tig >> 1);   // shuffle sources
    const int s2l = s0l + 2;
    const bool e1 = (tig & 1) != 0;

    for (int it = 0; it < Ln / 64; it++) {
        float* KP = sm + OFF_KP + (it & 1) * NKP;
        float* VP = sm + OFF_VP + (it & 1) * NVP;

        // pack stores from prefetched regs
        #pragma unroll
        for (int q4 = 0; q4 < 4; q4++) {
            const int c0 = kcol0 + q4 * 4;
            const int krgn = (c0 >> 3) * 8 + (krow >> 3);
            const int vrgn = (krow >> 3) * 8 + (c0 >> 3);
            const int nn = krow & 7;
            const int cb = c0 & 7;
            const float4 kv = kvr[q4];
            const float4 vv = vvr[q4];
            KP[b_idx(krgn, cb + 0, nn)] = tf32r(kv.x);
            KP[b_idx(krgn, cb + 1, nn)] = tf32r(kv.y);
            KP[b_idx(krgn, cb + 2, nn)] = tf32r(kv.z);
            KP[b_idx(krgn, cb + 3, nn)] = tf32r(kv.w);
            VP[b_idx(vrgn, nn, cb + 0)] = tf32r(vv.x);
            VP[b_idx(vrgn, nn, cb + 1)] = tf32r(vv.y);
            VP[b_idx(vrgn, nn, cb + 2)] = tf32r(vv.z);
            VP[b_idx(vrgn, nn, cb + 3)] = tf32r(vv.w);
        }
        __syncthreads();   // KV visible; prev iter fully done (Q on it=0)

        if (it + 1 < Ln / 64) {       // pipelined loads for next KV tile
            const int kt = (it + 1) * 64;
            #pragma unroll
            for (int q4 = 0; q4 < 4; q4++) {
                kvr[q4] = *(const float4*)&kb[(size_t)(kt + krow) * DH + kcol0 + q4 * 4];
                vvr[q4] = *(const float4*)&vb[(size_t)(kt + krow) * DH + kcol0 + q4 * 4];
            }
        }

        // MMA1: S[16,64] per warp = Q . K^T  (contraction c=64)
        float s[8][4] = {};
        #pragma unroll
        for (int ks = 0; ks < 8; ks++) {
            uint32_t aq[4];
            a_frag(aq, QP, wm * 8 + ks, g, tig);
            #pragma unroll
            for (int nt = 0; nt < 8; nt++) {
                uint32_t bf[2];
                b_frag(bf, KP, ks * 8 + nt, g, tig);
                mma8(s[nt], aq, bf);
            }
        }

        // exp + warp-local row sums; round P to tf32 in registers
        #pragma unroll
        for (int nt = 0; nt < 8; nt++) {
            #pragma unroll
            for (int reg = 0; reg < 4; reg++) {
                const float e = __expf(s[nt][reg]);
                ps_tot[reg >> 1] += e;
                s[nt][reg] = tf32r(e);
            }
        }

        // MMA2: O[16,64] += P . V  (contraction key=64, A via shuffle transpose)
        #pragma unroll
        for (int ks2 = 0; ks2 < 8; ks2++) {
            const float v00 = __shfl_sync(0xffffffffu, s[ks2][0], s0l);
            const float v01 = __shfl_sync(0xffffffffu, s[ks2][1], s0l);
            const float v10 = __shfl_sync(0xffffffffu, s[ks2][2], s0l);
            const float v11 = __shfl_sync(0xffffffffu, s[ks2][3], s0l);
            const float v20 = __shfl_sync(0xffffffffu, s[ks2][0], s2l);
            const float v21 = __shfl_sync(0xffffffffu, s[ks2][1], s2l);
            const float v30 = __shfl_sync(0xffffffffu, s[ks2][2], s2l);
            const float v31 = __shfl_sync(0xffffffffu, s[ks2][3], s2l);
            uint32_t a[4];
            a[0] = fbits(e1 ? v01 : v00);
            a[1] = fbits(e1 ? v11 : v10);
            a[2] = fbits(e1 ? v21 : v20);
            a[3] = fbits(e1 ? v31 : v30);
            #pragma unroll
            for (int nt2 = 0; nt2 < 8; nt2++) {
                uint32_t bf[2];
                b_frag(bf, VP, ks2 * 8 + nt2, g, tig);
                mma8(oacc[nt2], a, bf);
            }
        }
    }

    // warp-local row-sum completion: reduce over the 4 tig lanes
    float ls[2];
    #pragma unroll
    for (int hf = 0; hf < 2; hf++) {
        float v = ps_tot[hf];
        v += __shfl_xor_sync(0xffffffffu, v, 1);
        v += __shfl_xor_sync(0xffffffffu, v, 2);
        ls[hf] = 1.0f / v;
    }

    const int b = bh >> 3, h = bh & 7;
    #pragma unroll
    for (int nt2 = 0; nt2 < 8; nt2++) {
        #pragma unroll
        for (int reg = 0; reg < 4; reg++) {
            const int hf  = reg >> 1;
            const int row = wm * 16 + g + hf * 8;
            const int c   = nt2 * 8 + tig * 2 + (reg & 1);
            g_o[((size_t)b * HID + h * 64 + c) * Ln + lq0 + row] =
                oacc[nt2][reg] * ls[hf];
        }
    }
}

// ---------------------------------------------------------------------------
// Kernel 3: output projection.  out[b] = w_out[512,512] @ g_o_b[512,2048] + bias
// Same pipelined double-buffered structure as qkv_mma.
// ---------------------------------------------------------------------------
__global__ __launch_bounds__(256, 2) void outp_mma(const float* __restrict__ w,
                                                   const float* __restrict__ bias,
                                                   float* __restrict__ out) {
    extern __shared__ float dsm[];
    const int t    = threadIdx.x;
    const int w8   = t >> 5;
    const int lane = t & 31;
    const int g    = lane >> 2;
    const int tig  = lane & 3;
    const int wm   = w8 & 3;
    const int wn   = w8 >> 2;
    const int ltile = blockIdx.x * 128;
    const int bm    = blockIdx.y;     // 0..3
    const int b     = blockIdx.z;

    const float* xb = g_o + (size_t)b * HID * Ln;

    const int wr = t >> 3;
    const int wc = (t & 7) * 4;
    const int xr = t >> 5;
    const int xc = (t & 31) * 4;

    float4 wv[4], xv[4];
    #pragma unroll
    for (int jj = 0; jj < 4; jj++) {
        wv[jj] = *(const float4*)&w[(size_t)(bm * 128 + jj * 32 + wr) * HID + wc];
        xv[jj] = *(const float4*)&xb[(size_t)(jj * 8 + xr) * Ln + ltile + xc];
    }

    float acc[16][4] = {};

    for (int ci = 0; ci < HID / 32; ci++) {
        float* WsP = dsm + (ci & 1) * NWP;
        float* XsP = dsm + 2 * NWP + (ci & 1) * NXP;

        #pragma unroll
        for (int jj = 0; jj < 4; jj++) {
            const int r = jj * 32 + wr;
            const int region = (r >> 4) * 4 + (wc >> 3);
            const int rr = r & 15;
            const int kb = wc & 7;
            const float4 v = wv[jj];
            WsP[a_idx(region, rr, kb + 0)] = tf32r(v.x);
            WsP[a_idx(region, rr, kb + 1)] = tf32r(v.y);
            WsP[a_idx(region, rr, kb + 2)] = tf32r(v.z);
            WsP[a_idx(region, rr, kb + 3)] = tf32r(v.w);
        }
        #pragma unroll
        for (int jj = 0; jj < 4; jj++) {
            const int r = jj * 8 + xr;
            const int region = (r >> 3) * 16 + (xc >> 3);
            const int kk = r & 7;
            const int nb = xc & 7;
            const float4 v = xv[jj];
            XsP[b_idx(region, kk, nb + 0)] = tf32r(v.x);
            XsP[b_idx(region, kk, nb + 1)] = tf32r(v.y);
            XsP[b_idx(region, kk, nb + 2)] = tf32r(v.z);
            XsP[b_idx(region, kk, nb + 3)] = tf32r(v.w);
        }
        __syncthreads();

        if (ci + 1 < HID / 32) {
            const int kc = (ci + 1) * 32;
            #pragma unroll
            for (int jj = 0; jj < 4; jj++) {
                wv[jj] = *(const float4*)&w[(size_t)(bm * 128 + jj * 32 + wr) * HID + kc + wc];
                xv[jj] = *(const float4*)&xb[(size_t)(kc + jj * 8 + xr) * Ln + ltile + xc];
            }
        }

        #pragma unroll
        for (int ks = 0; ks < 4; ks++) {
            uint32_t a[2][4];
            a_frag(a[0], WsP, (wm * 2 + 0) * 4 + ks, g, tig);
            a_frag(a[1], WsP, (wm * 2 + 1) * 4 + ks, g, tig);
            #pragma unroll
            for (int nt = 0; nt < 8; nt++) {
                uint32_t bf[2];
                b_frag(bf, XsP, ks * 16 + wn * 8 + nt, g, tig);
                mma8(acc[nt], a[0], bf);
                mma8(acc[8 + nt], a[1], bf);
            }
        }
    }

    #pragma unroll
    for (int mt = 0; mt < 2; mt++) {
        #pragma unroll
        for (int nt = 0; nt < 8; nt++) {
            #pragma unroll
            for (int reg = 0; reg < 4; reg++) {
                const int m = bm * 128 + wm * 32 + mt * 16 + g + ((reg >= 2) ? 8 : 0);
                const int l = ltile + wn * 64 + nt * 8 + tig * 2 + (reg & 1);
                out[((size_t)b * DIM + m) * Ln + l] = acc[mt * 8 + nt][reg] + bias[m];
            }
        }
    }
}

// ---------------------------------------------------------------------------
extern "C" void kernel_launch(void* const* d_in, const int* in_sizes, int n_in,
                              void* d_out, int out_size) {
    const float* x     = (const float*)d_in[0];
    const float* w_qkv = (const float*)d_in[1];
    const float* w_out = (const float*)d_in[2];
    const float* b_out = (const float*)d_in[3];
    float* out = (float*)d_out;

    cudaFuncSetAttribute(qkv_mma,  cudaFuncAttributeMaxDynamicSharedMemorySize, GEMM_SMEM);
    cudaFuncSetAttribute(attn_mma, cudaFuncAttributeMaxDynamicSharedMemorySize, ATTN_SMEM);
    cudaFuncSetAttribute(outp_mma, cudaFuncAttributeMaxDynamicSharedMemorySize, GEMM_SMEM);

    qkv_mma<<<dim3(Ln / 128, (3 * HID) / 128, Bn), 256, GEMM_SMEM>>>(x, w_qkv);
    attn_mma<<<dim3(Ln / 128, Bn * Hn), 256, ATTN_SMEM>>>();
    outp_mma<<<dim3(Ln / 128, HID / 128, Bn), 256, GEMM_SMEM>>>(w_out, b_out, out);
}

// round 11
// speedup vs baseline: 1.1029x; 1.1029x over previous
#include <cuda_runtime.h>
#include <cstdint>

// Attention_41480794145302 — mma.sync tf32, frag-packed smem.
// qkv/outp: R9 single-buffer (verified fastest). attn: shuffle-transpose P
// + Q-fragments hoisted to registers + double-buffered KV (1 sync/iter).
// x:[B,512,L]  w_qkv:[1536,512]  w_out:[512,512]  b_out:[512]  out:[B,512,L]

namespace {
constexpr int Bn  = 4;
constexpr int DIM = 512;
constexpr int Ln  = 2048;
constexpr int Hn  = 8;
constexpr int DH  = 64;
constexpr int HID = 512;
constexpr float SCALE = 0.125f;   // 64^-0.5
}

// scratch (allocation-free rule: __device__ globals)
__device__ float g_q[Bn * Hn * Ln * DH];  // [b,h,l,c]
__device__ float g_k[Bn * Hn * Ln * DH];  // [b,h,l,c]
__device__ float g_v[Bn * Hn * Ln * DH];  // [b,h,l,c]
__device__ float g_o[Bn * HID * Ln];      // [b, h*64+c, l]

__device__ __forceinline__ float tf32r(float f) {   // round-to-nearest tf32
    uint32_t u;
    asm("cvt.rna.tf32.f32 %0, %1;" : "=r"(u) : "f"(f));
    return __uint_as_float(u);
}
__device__ __forceinline__ uint32_t fbits(float f) { return __float_as_uint(f); }

// D += A(16x8,row) * B(8x8,col)  tf32
__device__ __forceinline__ void mma8(float* c, const uint32_t* a, const uint32_t* b) {
    asm volatile(
        "mma.sync.aligned.m16n8k8.row.col.f32.tf32.tf32.f32 "
        "{%0,%1,%2,%3}, {%4,%5,%6,%7}, {%8,%9}, {%0,%1,%2,%3};"
        : "+f"(c[0]), "+f"(c[1]), "+f"(c[2]), "+f"(c[3])
        : "r"(a[0]), "r"(a[1]), "r"(a[2]), "r"(a[3]), "r"(b[0]), "r"(b[1]));
}

// ---------------------------------------------------------------------------
// Fragment-packed smem layouts (validated R6 scheme).
// ---------------------------------------------------------------------------
__device__ __forceinline__ int a_idx(int region, int rr, int kk) {
    const int g = rr & 7;
    const int lane = (g * 4 + (kk & 3)) ^ ((g >> 1) & 3);
    return region * 132 + lane * 4 + (rr >> 3) + 2 * (kk >> 2);
}
__device__ __forceinline__ void a_frag(uint32_t* a, const float* base, int region,
                                       int g, int tig) {
    const float4 f = *(const float4*)&base[region * 132 + (((g * 4 + tig) ^ ((g >> 1) & 3)) * 4)];
    a[0] = fbits(f.x); a[1] = fbits(f.y); a[2] = fbits(f.z); a[3] = fbits(f.w);
}
__device__ __forceinline__ int b_idx(int region, int kk, int nn) {
    const int m = (region ^ (region >> 3)) & 3;
    return region * 66 + (((nn * 4 + (kk & 3)) ^ m) * 2) + (kk >> 2);
}
__device__ __forceinline__ void b_frag(uint32_t* b, const float* base, int region,
                                       int g, int tig) {
    const int m = (region ^ (region >> 3)) & 3;
    const float2 f = *(const float2*)&base[region * 66 + (((g * 4 + tig) ^ m) * 2)];
    b[0] = fbits(f.x); b[1] = fbits(f.y);
}

// ---------------------------------------------------------------------------
// Kernel 1: QKV projection (R9 version — verified 155us).
// Block tile 128(M) x 128(N), K-chunk 32, 8 warps; warp tile 32x64.
// ---------------------------------------------------------------------------
__global__ __launch_bounds__(256, 2) void qkv_mma(const float* __restrict__ x,
                                                  const float* __restrict__ w) {
    __shared__ float WsP[32 * 132];   // A-pack: 8 mtiles x 4 ktiles
    __shared__ float XsP[64 * 66];    // B-pack: 4 ktiles x 16 ntiles

    const int t    = threadIdx.x;
    const int w8   = t >> 5;
    const int lane = t & 31;
    const int g    = lane >> 2;
    const int tig  = lane & 3;
    const int wm   = w8 & 3;
    const int wn   = w8 >> 2;
    const int ltile = blockIdx.x * 128;
    const int bm    = blockIdx.y;
    const int b     = blockIdx.z;

    const float* xb = x + (size_t)b * DIM * Ln;

    float acc[16][4] = {};

    for (int kc = 0; kc < DIM; kc += 32) {
        __syncthreads();
        #pragma unroll
        for (int jj = 0; jj < 4; jj++) {
            const int pos = t + 256 * jj;
            const int r   = pos >> 3;
            const int c4  = (pos & 7) * 4;
            const float4 v = *(const float4*)&w[(size_t)(bm * 128 + r) * DIM + kc + c4];
            const int region = (r >> 4) * 4 + (c4 >> 3);
            const int rr = r & 15;
            const int kb = c4 & 7;
            WsP[a_idx(region, rr, kb + 0)] = tf32r(v.x);
            WsP[a_idx(region, rr, kb + 1)] = tf32r(v.y);
            WsP[a_idx(region, rr, kb + 2)] = tf32r(v.z);
            WsP[a_idx(region, rr, kb + 3)] = tf32r(v.w);
        }
        #pragma unroll
        for (int jj = 0; jj < 4; jj++) {
            const int pos = t + 256 * jj;
            const int r   = pos >> 5;
            const int c4  = (pos & 31) * 4;
            const float4 v = *(const float4*)&xb[(size_t)(kc + r) * Ln + ltile + c4];
            const int region = (r >> 3) * 16 + (c4 >> 3);
            const int kk = r & 7;
            const int nb = c4 & 7;
            XsP[b_idx(region, kk, nb + 0)] = tf32r(v.x);
            XsP[b_idx(region, kk, nb + 1)] = tf32r(v.y);
            XsP[b_idx(region, kk, nb + 2)] = tf32r(v.z);
            XsP[b_idx(region, kk, nb + 3)] = tf32r(v.w);
        }
        __syncthreads();

        #pragma unroll
        for (int ks = 0; ks < 4; ks++) {
            uint32_t a[2][4];
            a_frag(a[0], WsP, (wm * 2 + 0) * 4 + ks, g, tig);
            a_frag(a[1], WsP, (wm * 2 + 1) * 4 + ks, g, tig);
            #pragma unroll
            for (int nt = 0; nt < 8; nt++) {
                uint32_t bf[2];
                b_frag(bf, XsP, ks * 16 + wn * 8 + nt, g, tig);
                mma8(acc[nt], a[0], bf);
                mma8(acc[8 + nt], a[1], bf);
            }
        }
    }

    #pragma unroll
    for (int mt = 0; mt < 2; mt++) {
        #pragma unroll
        for (int nt = 0; nt < 8; nt++) {
            #pragma unroll
            for (int reg = 0; reg < 4; reg++) {
                const int m = bm * 128 + wm * 32 + mt * 16 + g + ((reg >= 2) ? 8 : 0);
                const int l = ltile + wn * 64 + nt * 8 + tig * 2 + (reg & 1);
                const int tile = m >> 6;
                const int sec  = tile >> 3;
                const int h    = tile & 7;
                const int c    = m & 63;
                float val = acc[mt * 8 + nt][reg];
                if (sec == 0) val *= SCALE;
                float* dst = (sec == 0) ? g_q : ((sec == 1) ? g_k : g_v);
                dst[((size_t)(b * Hn + h) * Ln + l) * DH + c] = val;
            }
        }
    }
}

// ---------------------------------------------------------------------------
// Kernel 2: flash attention.  Block = 128 q-rows; KV tiles of 64; 8 warps,
// warp tile 16 rows x 64 keys.  Q A-fragments hoisted to registers (loop-
// invariant).  P stays in registers (shuffle transpose).  Double-buffered KV
// written straight from global; 1 __syncthreads per iteration.
// ---------------------------------------------------------------------------
namespace {
constexpr int NQP = 64 * 132;   // Q A-pack: 8 mtiles x 8 ktiles
constexpr int NKP = 64 * 66;    // K B-pack
constexpr int NVP = 64 * 66;    // V B-pack
constexpr int OFF_QP = 0;
constexpr int OFF_KP = OFF_QP + NQP;
constexpr int OFF_VP = OFF_KP + 2 * NKP;
constexpr int ATTN_SMEM = (OFF_VP + 2 * NVP) * 4;   // 101376 B
}

__global__ __launch_bounds__(256, 2) void attn_mma() {
    extern __shared__ float sm[];
    float* QP = sm + OFF_QP;

    const int t    = threadIdx.x;
    const int w8   = t >> 5;
    const int lane = t & 31;
    const int g    = lane >> 2;
    const int tig  = lane & 3;
    const int wm   = w8;              // 16-row slice per warp
    const int bh   = blockIdx.y;
    const int lq0  = blockIdx.x * 128;

    const float* qb = g_q + (size_t)bh * Ln * DH;
    const float* kb = g_k + (size_t)bh * Ln * DH;
    const float* vb = g_v + (size_t)bh * Ln * DH;

    // load Q tile: 128 x 64 -> A-pack in smem
    #pragma unroll
    for (int jj = 0; jj < 8; jj++) {
        const int pos = t + 256 * jj;
        const int r   = pos >> 4;
        const int c4  = (pos & 15) * 4;
        const float4 v = *(const float4*)&qb[(size_t)(lq0 + r) * DH + c4];
        const int region = (r >> 4) * 8 + (c4 >> 3);
        const int rr = r & 15;
        const int kb2 = c4 & 7;
        QP[a_idx(region, rr, kb2 + 0)] = tf32r(v.x);
        QP[a_idx(region, rr, kb2 + 1)] = tf32r(v.y);
        QP[a_idx(region, rr, kb2 + 2)] = tf32r(v.z);
        QP[a_idx(region, rr, kb2 + 3)] = tf32r(v.w);
    }
    __syncthreads();

    // hoist Q fragments to registers (loop-invariant A operand)
    uint32_t qf[8][4];
    #pragma unroll
    for (int ks = 0; ks < 8; ks++)
        a_frag(qf[ks], QP, wm * 8 + ks, g, tig);

    // per-thread KV load coords: row 0..63, 16 consecutive c cols
    const int krow  = t >> 2;
    const int kcol0 = (t & 3) * 16;

    float oacc[8][4] = {};            // [nt2][reg]
    float ps_tot[2] = {0.0f, 0.0f};   // row-sum accumulators (rows g, g+8)

    const int s0l = (lane & ~3) + (tig >> 1);   // shuffle sources
    const int s2l = s0l + 2;
    const bool e1 = (tig & 1) != 0;

    for (int it = 0; it < Ln / 64; it++) {
        float* KP = sm + OFF_KP + (it & 1) * NKP;
        float* VP = sm + OFF_VP + (it & 1) * NVP;
        const int kt = it * 64;

        // load + pack KV straight from global (no prefetch registers)
        #pragma unroll
        for (int q4 = 0; q4 < 4; q4++) {
            const int c0 = kcol0 + q4 * 4;
            const float4 kv = *(const float4*)&kb[(size_t)(kt + krow) * DH + c0];
            const float4 vv = *(const float4*)&vb[(size_t)(kt + krow) * DH + c0];
            const int krgn = (c0 >> 3) * 8 + (krow >> 3);
            const int vrgn = (krow >> 3) * 8 + (c0 >> 3);
            const int nn = krow & 7;
            const int cb = c0 & 7;
            KP[b_idx(krgn, cb + 0, nn)] = tf32r(kv.x);
            KP[b_idx(krgn, cb + 1, nn)] = tf32r(kv.y);
            KP[b_idx(krgn, cb + 2, nn)] = tf32r(kv.z);
            KP[b_idx(krgn, cb + 3, nn)] = tf32r(kv.w);
            VP[b_idx(vrgn, nn, cb + 0)] = tf32r(vv.x);
            VP[b_idx(vrgn, nn, cb + 1)] = tf32r(vv.y);
            VP[b_idx(vrgn, nn, cb + 2)] = tf32r(vv.z);
            VP[b_idx(vrgn, nn, cb + 3)] = tf32r(vv.w);
        }
        __syncthreads();   // this buffer visible; other buffer free (proof in R10)

        // MMA1: S[16,64] per warp = Q . K^T  (A from registers)
        float s[8][4] = {};
        #pragma unroll
        for (int ks = 0; ks < 8; ks++) {
            #pragma unroll
            for (int nt = 0; nt < 8; nt++) {
                uint32_t bf[2];
                b_frag(bf, KP, ks * 8 + nt, g, tig);
                mma8(s[nt], qf[ks], bf);
            }
        }

        // exp + warp-local row sums; round P to tf32 in registers
        #pragma unroll
        for (int nt = 0; nt < 8; nt++) {
            #pragma unroll
            for (int reg = 0; reg < 4; reg++) {
                const float e = __expf(s[nt][reg]);
                ps_tot[reg >> 1] += e;
                s[nt][reg] = tf32r(e);
            }
        }

        // MMA2: O[16,64] += P . V  (A via shuffle transpose)
        #pragma unroll
        for (int ks2 = 0; ks2 < 8; ks2++) {
            const float v00 = __shfl_sync(0xffffffffu, s[ks2][0], s0l);
            const float v01 = __shfl_sync(0xffffffffu, s[ks2][1], s0l);
            const float v10 = __shfl_sync(0xffffffffu, s[ks2][2], s0l);
            const float v11 = __shfl_sync(0xffffffffu, s[ks2][3], s0l);
            const float v20 = __shfl_sync(0xffffffffu, s[ks2][0], s2l);
            const float v21 = __shfl_sync(0xffffffffu, s[ks2][1], s2l);
            const float v30 = __shfl_sync(0xffffffffu, s[ks2][2], s2l);
            const float v31 = __shfl_sync(0xffffffffu, s[ks2][3], s2l);
            uint32_t a[4];
            a[0] = fbits(e1 ? v01 : v00);
            a[1] = fbits(e1 ? v11 : v10);
            a[2] = fbits(e1 ? v21 : v20);
            a[3] = fbits(e1 ? v31 : v30);
            #pragma unroll
            for (int nt2 = 0; nt2 < 8; nt2++) {
                uint32_t bf[2];
                b_frag(bf, VP, ks2 * 8 + nt2, g, tig);
                mma8(oacc[nt2], a, bf);
            }
        }
    }

    // warp-local row-sum completion: reduce over the 4 tig lanes
    float ls[2];
    #pragma unroll
    for (int hf = 0; hf < 2; hf++) {
        float v = ps_tot[hf];
        v += __shfl_xor_sync(0xffffffffu, v, 1);
        v += __shfl_xor_sync(0xffffffffu, v, 2);
        ls[hf] = 1.0f / v;
    }

    const int b = bh >> 3, h = bh & 7;
    #pragma unroll
    for (int nt2 = 0; nt2 < 8; nt2++) {
        #pragma unroll
        for (int reg = 0; reg < 4; reg++) {
            const int hf  = reg >> 1;
            const int row = wm * 16 + g + hf * 8;
            const int c   = nt2 * 8 + tig * 2 + (reg & 1);
            g_o[((size_t)b * HID + h * 64 + c) * Ln + lq0 + row] =
                oacc[nt2][reg] * ls[hf];
        }
    }
}

// ---------------------------------------------------------------------------
// Kernel 3: output projection (R9 version).
// ---------------------------------------------------------------------------
__global__ __launch_bounds__(256, 2) void outp_mma(const float* __restrict__ w,
                                                   const float* __restrict__ bias,
                                                   float* __restrict__ out) {
    __shared__ float WsP[32 * 132];
    __shared__ float XsP[64 * 66];

    const int t    = threadIdx.x;
    const int w8   = t >> 5;
    const int lane = t & 31;
    const int g    = lane >> 2;
    const int tig  = lane & 3;
    const int wm   = w8 & 3;
    const int wn   = w8 >> 2;
    const int ltile = blockIdx.x * 128;
    const int bm    = blockIdx.y;
    const int b     = blockIdx.z;

    const float* xb = g_o + (size_t)b * HID * Ln;

    float acc[16][4] = {};

    for (int kc = 0; kc < HID; kc += 32) {
        __syncthreads();
        #pragma unroll
        for (int jj = 0; jj < 4; jj++) {
            const int pos = t + 256 * jj;
            const int r   = pos >> 3;
            const int c4  = (pos & 7) * 4;
            const float4 v = *(const float4*)&w[(size_t)(bm * 128 + r) * HID + kc + c4];
            const int region = (r >> 4) * 4 + (c4 >> 3);
            const int rr = r & 15;
            const int kb = c4 & 7;
            WsP[a_idx(region, rr, kb + 0)] = tf32r(v.x);
            WsP[a_idx(region, rr, kb + 1)] = tf32r(v.y);
            WsP[a_idx(region, rr, kb + 2)] = tf32r(v.z);
            WsP[a_idx(region, rr, kb + 3)] = tf32r(v.w);
        }
        #pragma unroll
        for (int jj = 0; jj < 4; jj++) {
            const int pos = t + 256 * jj;
            const int r   = pos >> 5;
            const int c4  = (pos & 31) * 4;
            const float4 v = *(const float4*)&xb[(size_t)(kc + r) * Ln + ltile + c4];
            const int region = (r >> 3) * 16 + (c4 >> 3);
            const int kk = r & 7;
            const int nb = c4 & 7;
            XsP[b_idx(region, kk, nb + 0)] = tf32r(v.x);
            XsP[b_idx(region, kk, nb + 1)] = tf32r(v.y);
            XsP[b_idx(region, kk, nb + 2)] = tf32r(v.z);
            XsP[b_idx(region, kk, nb + 3)] = tf32r(v.w);
        }
        __syncthreads();

        #pragma unroll
        for (int ks = 0; ks < 4; ks++) {
            uint32_t a[2][4];
            a_frag(a[0], WsP, (wm * 2 + 0) * 4 + ks, g, tig);
            a_frag(a[1], WsP, (wm * 2 + 1) * 4 + ks, g, tig);
            #pragma unroll
            for (int nt = 0; nt < 8; nt++) {
                uint32_t bf[2];
                b_frag(bf, XsP, ks * 16 + wn * 8 + nt, g, tig);
                mma8(acc[nt], a[0], bf);
                mma8(acc[8 + nt], a[1], bf);
            }
        }
    }

    #pragma unroll
    for (int mt = 0; mt < 2; mt++) {
        #pragma unroll
        for (int nt = 0; nt < 8; nt++) {
            #pragma unroll
            for (int reg = 0; reg < 4; reg++) {
                const int m = bm * 128 + wm * 32 + mt * 16 + g + ((reg >= 2) ? 8 : 0);
                const int l = ltile + wn * 64 + nt * 8 + tig * 2 + (reg & 1);
                out[((size_t)b * DIM + m) * Ln + l] = acc[mt * 8 + nt][reg] + bias[m];
            }
        }
    }
}

// ---------------------------------------------------------------------------
extern "C" void kernel_launch(void* const* d_in, const int* in_sizes, int n_in,
                              void* d_out, int out_size) {
    const float* x     = (const float*)d_in[0];
    const float* w_qkv = (const float*)d_in[1];
    const float* w_out = (const float*)d_in[2];
    const float* b_out = (const float*)d_in[3];
    float* out = (float*)d_out;

    cudaFuncSetAttribute(attn_mma, cudaFuncAttributeMaxDynamicSharedMemorySize, ATTN_SMEM);

    qkv_mma<<<dim3(Ln / 128, (3 * HID) / 128, Bn), 256>>>(x, w_qkv);
    attn_mma<<<dim3(Ln / 128, Bn * Hn), 256, ATTN_SMEM>>>();
    outp_mma<<<dim3(Ln / 128, HID / 128, Bn), 256>>>(w_out, b_out, out);
}

// round 12
// speedup vs baseline: 1.8936x; 1.7170x over previous
#include <cuda_runtime.h>
#include <cuda_fp16.h>
#include <cstdint>

// Attention_41480794145302 — mma.sync fp16 m16n8k16 (f32 accum), frag-packed
// smem.  Same structure as R11; P->MMA2 needs no transpose (fp16 A-frag layout
// == C-frag layout).  All global tensors f32; fp16 conversion in pack stores.
// x:[B,512,L]  w_qkv:[1536,512]  w_out:[512,512]  b_out:[512]  out:[B,512,L]

namespace {
constexpr int Bn  = 4;
constexpr int DIM = 512;
constexpr int Ln  = 2048;
constexpr int Hn  = 8;
constexpr int DH  = 64;
constexpr int HID = 512;
constexpr float SCALE = 0.125f;   // 64^-0.5
}

// scratch (allocation-free rule: __device__ globals)
__device__ float g_q[Bn * Hn * Ln * DH];  // [b,h,l,c]
__device__ float g_k[Bn * Hn * Ln * DH];  // [b,h,l,c]
__device__ float g_v[Bn * Hn * Ln * DH];  // [b,h,l,c]
__device__ float g_o[Bn * HID * Ln];      // [b, h*64+c, l]

__device__ __forceinline__ uint32_t f2h2(float lo, float hi) {
    __half2 h = __floats2half2_rn(lo, hi);
    return *(uint32_t*)&h;
}

// D += A(16x16,row) * B(16x8,col)  fp16, f32 accum
__device__ __forceinline__ void mma16(float* c, const uint32_t* a, const uint32_t* b) {
    asm volatile(
        "mma.sync.aligned.m16n8k16.row.col.f32.f16.f16.f32 "
        "{%0,%1,%2,%3}, {%4,%5,%6,%7}, {%8,%9}, {%0,%1,%2,%3};"
        : "+f"(c[0]), "+f"(c[1]), "+f"(c[2]), "+f"(c[3])
        : "r"(a[0]), "r"(a[1]), "r"(a[2]), "r"(a[3]), "r"(b[0]), "r"(b[1]));
}

// ---------------------------------------------------------------------------
// fp16 fragment-packed smem layouts (words = uint32 = half2).
// A region = one 16(M)x16(K) tile: 128 words + pad -> 132.  One LDS.128/frag.
//   element (rr,kk): lane=((rr&7)*4+((kk>>1)&3))^((rr>>1)&3),
//   word j=(rr>>3)+2*(kk>>3), half=kk&1.
// B region = one 16(K)x8(N) tile: 64 words + pad -> 66.  One LDS.64/frag.
//   element (kk,nn): lane=(nn*4+((kk>>1)&3))^swz(region), word j=kk>>3.
// ---------------------------------------------------------------------------
__device__ __forceinline__ int ha_word(int region, int rr, int kk) {
    const int lane = (((rr & 7) * 4 + ((kk >> 1) & 3)) ^ ((rr >> 1) & 3));
    return region * 132 + lane * 4 + (rr >> 3) + 2 * (kk >> 3);
}
__device__ __forceinline__ void a_frag16(uint32_t* a, const uint32_t* base,
                                         int region, int g, int tig) {
    const uint4 f = *(const uint4*)&base[region * 132 + (((g * 4 + tig) ^ ((g >> 1) & 3)) * 4)];
    a[0] = f.x; a[1] = f.y; a[2] = f.z; a[3] = f.w;
}
__device__ __forceinline__ int hb_word(int region, int kk, int nn) {
    const int m = (region ^ (region >> 3)) & 3;
    return region * 66 + (((nn * 4 + ((kk >> 1) & 3)) ^ m) * 2) + (kk >> 3);
}
__device__ __forceinline__ void b_frag16(uint32_t* b, const uint32_t* base,
                                         int region, int g, int tig) {
    const int m = (region ^ (region >> 3)) & 3;
    const uint2 f = *(const uint2*)&base[region * 66 + (((g * 4 + tig) ^ m) * 2)];
    b[0] = f.x; b[1] = f.y;
}

// ---------------------------------------------------------------------------
// Kernel 1: QKV projection.  C[1536,2048] = w_qkv[1536,512] @ x_b[512,2048]
// Block tile 128(M) x 128(N), K-chunk 32 (= 2 k16 steps), 8 warps, warp 32x64.
// ---------------------------------------------------------------------------
__global__ __launch_bounds__(256, 2) void qkv_mma(const float* __restrict__ x,
                                                  const float* __restrict__ w) {
    __shared__ uint32_t WsP[16 * 132];   // A-pack: 8 mtiles x 2 ktiles
    __shared__ uint32_t XsP[32 * 66];    // B-pack: 2 ktiles x 16 ntiles

    const int t    = threadIdx.x;
    const int w8   = t >> 5;
    const int lane = t & 31;
    const int g    = lane >> 2;
    const int tig  = lane & 3;
    const int wm   = w8 & 3;
    const int wn   = w8 >> 2;
    const int ltile = blockIdx.x * 128;
    const int bm    = blockIdx.y;
    const int b     = blockIdx.z;

    const float* xb = x + (size_t)b * DIM * Ln;

    float acc[16][4] = {};

    for (int kc = 0; kc < DIM; kc += 32) {
        __syncthreads();
        // W tile 128x32 -> A-pack
        #pragma unroll
        for (int jj = 0; jj < 4; jj++) {
            const int pos = t + 256 * jj;
            const int r   = pos >> 3;
            const int c4  = (pos & 7) * 4;
            const float4 v = *(const float4*)&w[(size_t)(bm * 128 + r) * DIM + kc + c4];
            const int region = (r >> 4) * 2 + (c4 >> 4);
            const int rr = r & 15;
            const int kk = c4 & 15;
            WsP[ha_word(region, rr, kk)]     = f2h2(v.x, v.y);
            WsP[ha_word(region, rr, kk + 2)] = f2h2(v.z, v.w);
        }
        // X tile 32x128 -> B-pack (pairs along k via two row loads)
        #pragma unroll
        for (int jj = 0; jj < 2; jj++) {
            const int p  = t >> 4;                    // k-pair 0..15
            const int l0 = (t & 15) * 4 + jj * 64;
            const float4 A = *(const float4*)&xb[(size_t)(kc + 2 * p) * Ln + ltile + l0];
            const float4 B = *(const float4*)&xb[(size_t)(kc + 2 * p + 1) * Ln + ltile + l0];
            const int kk = (2 * p) & 15;
            const int kt2 = (2 * p) >> 4;
            XsP[hb_word(kt2 * 16 + ((l0 + 0) >> 3), kk, (l0 + 0) & 7)] = f2h2(A.x, B.x);
            XsP[hb_word(kt2 * 16 + ((l0 + 1) >> 3), kk, (l0 + 1) & 7)] = f2h2(A.y, B.y);
            XsP[hb_word(kt2 * 16 + ((l0 + 2) >> 3), kk, (l0 + 2) & 7)] = f2h2(A.z, B.z);
            XsP[hb_word(kt2 * 16 + ((l0 + 3) >> 3), kk, (l0 + 3) & 7)] = f2h2(A.w, B.w);
        }
        __syncthreads();

        #pragma unroll
        for (int ks = 0; ks < 2; ks++) {
            uint32_t a[2][4];
            a_frag16(a[0], WsP, (wm * 2 + 0) * 2 + ks, g, tig);
            a_frag16(a[1], WsP, (wm * 2 + 1) * 2 + ks, g, tig);
            #pragma unroll
            for (int nt = 0; nt < 8; nt++) {
                uint32_t bf[2];
                b_frag16(bf, XsP, ks * 16 + wn * 8 + nt, g, tig);
                mma16(acc[nt], a[0], bf);
                mma16(acc[8 + nt], a[1], bf);
            }
        }
    }

    // epilogue: scatter into heads layout (f32)
    #pragma unroll
    for (int mt = 0; mt < 2; mt++) {
        #pragma unroll
        for (int nt = 0; nt < 8; nt++) {
            #pragma unroll
            for (int reg = 0; reg < 4; reg++) {
                const int m = bm * 128 + wm * 32 + mt * 16 + g + ((reg >= 2) ? 8 : 0);
                const int l = ltile + wn * 64 + nt * 8 + tig * 2 + (reg & 1);
                const int tile = m >> 6;
                const int sec  = tile >> 3;
                const int h    = tile & 7;
                const int c    = m & 63;
                float val = acc[mt * 8 + nt][reg];
                if (sec == 0) val *= SCALE;
                float* dst = (sec == 0) ? g_q : ((sec == 1) ? g_k : g_v);
                dst[((size_t)(b * Hn + h) * Ln + l) * DH + c] = val;
            }
        }
    }
}

// ---------------------------------------------------------------------------
// Kernel 2: flash attention, fp16.  Block = 128 q-rows; KV tiles of 64;
// 8 warps, warp tile 16 rows x 64 keys.  Q A-frags hoisted to registers;
// P passes S-accumulators straight into MMA2 A-frags (no transpose, no smem).
// Double-buffered KV, 1 __syncthreads per iteration.
// ---------------------------------------------------------------------------
namespace {
constexpr int NQP = 32 * 132;   // Q A-pack: 8 mtiles x 4 ktiles (4224 w)
constexpr int NKP = 32 * 66;    // K B-pack: 4 ktiles(c16) x 8 ntiles (2112 w)
constexpr int NVP = 32 * 66;    // V B-pack: 4 ktiles(key16) x 8 ntiles(c8)
constexpr int OFF_QP = 0;
constexpr int OFF_KP = OFF_QP + NQP;
constexpr int OFF_VP = OFF_KP + 2 * NKP;
constexpr int ATTN_SMEM = (OFF_VP + 2 * NVP) * 4;   // 50688 B
}

__global__ __launch_bounds__(256, 2) void attn_mma() {
    extern __shared__ uint32_t sm[];
    uint32_t* QP = sm + OFF_QP;

    const int t    = threadIdx.x;
    const int w8   = t >> 5;
    const int lane = t & 31;
    const int g    = lane >> 2;
    const int tig  = lane & 3;
    const int wm   = w8;              // 16-row slice per warp
    const int bh   = blockIdx.y;
    const int lq0  = blockIdx.x * 128;

    const float* qb = g_q + (size_t)bh * Ln * DH;
    const float* kb = g_k + (size_t)bh * Ln * DH;
    const float* vb = g_v + (size_t)bh * Ln * DH;

    // Q tile 128x64 -> A-pack (pairs along c, adjacent in [l][c])
    #pragma unroll
    for (int jj = 0; jj < 8; jj++) {
        const int pos = t + 256 * jj;
        const int r   = pos >> 4;
        const int c4  = (pos & 15) * 4;
        const float4 v = *(const float4*)&qb[(size_t)(lq0 + r) * DH + c4];
        const int region = (r >> 4) * 4 + (c4 >> 4);
        const int rr = r & 15;
        const int kk = c4 & 15;
        QP[ha_word(region, rr, kk)]     = f2h2(v.x, v.y);
        QP[ha_word(region, rr, kk + 2)] = f2h2(v.z, v.w);
    }
    __syncthreads();

    // hoist Q fragments (loop-invariant A operand): 4 k16 steps
    uint32_t qf[4][4];
    #pragma unroll
    for (int ks = 0; ks < 4; ks++)
        a_frag16(qf[ks], QP, wm * 4 + ks, g, tig);

    float oacc[8][4] = {};            // [nt2][reg]
    float ps_tot[2] = {0.0f, 0.0f};   // row sums (rows g, g+8)

    for (int it = 0; it < Ln / 64; it++) {
        uint32_t* KP = sm + OFF_KP + (it & 1) * NKP;
        uint32_t* VP = sm + OFF_VP + (it & 1) * NVP;
        const int kt = it * 64;

        // K tile 64key x 64c -> B-pack (kk=c pairs adjacent)
        {
            const int key = t >> 2;
            const int c16 = (t & 3) * 16;
            #pragma unroll
            for (int u = 0; u < 4; u++) {
                const int c4 = c16 + u * 4;
                const float4 kv = *(const float4*)&kb[(size_t)(kt + key) * DH + c4];
                const int region = (c4 >> 4) * 8 + (key >> 3);
                const int kk = c4 & 15;
                const int nn = key & 7;
                KP[hb_word(region, kk, nn)]     = f2h2(kv.x, kv.y);
                KP[hb_word(region, kk + 2, nn)] = f2h2(kv.z, kv.w);
            }
        }
        // V tile 64key x 64c -> B-pack (kk=key pairs via two row loads)
        #pragma unroll
        for (int jj = 0; jj < 2; jj++) {
            const int p  = (t >> 4) + jj * 16;        // key-pair 0..31
            const int c4 = (t & 15) * 4;
            const float4 A = *(const float4*)&vb[(size_t)(kt + 2 * p) * DH + c4];
            const float4 B = *(const float4*)&vb[(size_t)(kt + 2 * p + 1) * DH + c4];
            const int kk = (2 * p) & 15;
            const int kt2 = (2 * p) >> 4;
            VP[hb_word(kt2 * 8 + ((c4 + 0) >> 3), kk, (c4 + 0) & 7)] = f2h2(A.x, B.x);
            VP[hb_word(kt2 * 8 + ((c4 + 1) >> 3), kk, (c4 + 1) & 7)] = f2h2(A.y, B.y);
            VP[hb_word(kt2 * 8 + ((c4 + 2) >> 3), kk, (c4 + 2) & 7)] = f2h2(A.z, B.z);
            VP[hb_word(kt2 * 8 + ((c4 + 3) >> 3), kk, (c4 + 3) & 7)] = f2h2(A.w, B.w);
        }
        __syncthreads();   // this buffer visible; other buffer's consumers done

        // MMA1: S[16,64] = Q . K^T  (contraction c=64, 4 k16 steps)
        float s[8][4] = {};
        #pragma unroll
        for (int ks = 0; ks < 4; ks++) {
            #pragma unroll
            for (int nt = 0; nt < 8; nt++) {
                uint32_t bf[2];
                b_frag16(bf, KP, ks * 8 + nt, g, tig);
                mma16(s[nt], qf[ks], bf);
            }
        }

        // exp + row sums + build fp16 A-frags for MMA2 directly from accums
        uint32_t pa[4][4];            // [ks2][a-regs]
        #pragma unroll
        for (int nt = 0; nt < 8; nt++) {
            const float e0 = __expf(s[nt][0]);
            const float e1 = __expf(s[nt][1]);
            const float e2 = __expf(s[nt][2]);
            const float e3 = __expf(s[nt][3]);
            ps_tot[0] += e0 + e1;
            ps_tot[1] += e2 + e3;
            pa[nt >> 1][(nt & 1) * 2 + 0] = f2h2(e0, e1);
            pa[nt >> 1][(nt & 1) * 2 + 1] = f2h2(e2, e3);
        }

        // MMA2: O[16,64] += P . V  (contraction key=64, 4 k16 steps)
        #pragma unroll
        for (int ks2 = 0; ks2 < 4; ks2++) {
            #pragma unroll
            for (int nt2 = 0; nt2 < 8; nt2++) {
                uint32_t bf[2];
                b_frag16(bf, VP, ks2 * 8 + nt2, g, tig);
                mma16(oacc[nt2], pa[ks2], bf);
            }
        }
    }

    // row-sum completion over the 4 tig lanes
    float ls[2];
    #pragma unroll
    for (int hf = 0; hf < 2; hf++) {
        float v = ps_tot[hf];
        v += __shfl_xor_sync(0xffffffffu, v, 1);
        v += __shfl_xor_sync(0xffffffffu, v, 2);
        ls[hf] = 1.0f / v;
    }

    const int b = bh >> 3, h = bh & 7;
    #pragma unroll
    for (int nt2 = 0; nt2 < 8; nt2++) {
        #pragma unroll
        for (int reg = 0; reg < 4; reg++) {
            const int hf  = reg >> 1;
            const int row = wm * 16 + g + hf * 8;
            const int c   = nt2 * 8 + tig * 2 + (reg & 1);
            g_o[((size_t)b * HID + h * 64 + c) * Ln + lq0 + row] =
                oacc[nt2][reg] * ls[hf];
        }
    }
}

// ---------------------------------------------------------------------------
// Kernel 3: output projection.  out[b] = w_out[512,512] @ g_o_b[512,2048]+bias
// Identical structure to qkv_mma (g_o is [channel][l], same as x).
// ---------------------------------------------------------------------------
__global__ __launch_bounds__(256, 2) void outp_mma(const float* __restrict__ w,
                                                   const float* __restrict__ bias,
                                                   float* __restrict__ out) {
    __shared__ uint32_t WsP[16 * 132];
    __shared__ uint32_t XsP[32 * 66];

    const int t    = threadIdx.x;
    const int w8   = t >> 5;
    const int lane = t & 31;
    const int g    = lane >> 2;
    const int tig  = lane & 3;
    const int wm   = w8 & 3;
    const int wn   = w8 >> 2;
    const int ltile = blockIdx.x * 128;
    const int bm    = blockIdx.y;
    const int b     = blockIdx.z;

    const float* xb = g_o + (size_t)b * HID * Ln;

    float acc[16][4] = {};

    for (int kc = 0; kc < HID; kc += 32) {
        __syncthreads();
        #pragma unroll
        for (int jj = 0; jj < 4; jj++) {
            const int pos = t + 256 * jj;
            const int r   = pos >> 3;
            const int c4  = (pos & 7) * 4;
            const float4 v = *(const float4*)&w[(size_t)(bm * 128 + r) * HID + kc + c4];
            const int region = (r >> 4) * 2 + (c4 >> 4);
            const int rr = r & 15;
            const int kk = c4 & 15;
            WsP[ha_word(region, rr, kk)]     = f2h2(v.x, v.y);
            WsP[ha_word(region, rr, kk + 2)] = f2h2(v.z, v.w);
        }
        #pragma unroll
        for (int jj = 0; jj < 2; jj++) {
            const int p  = t >> 4;
            const int l0 = (t & 15) * 4 + jj * 64;
            const float4 A = *(const float4*)&xb[(size_t)(kc + 2 * p) * Ln + ltile + l0];
            const float4 B = *(const float4*)&xb[(size_t)(kc + 2 * p + 1) * Ln + ltile + l0];
            const int kk = (2 * p) & 15;
            const int kt2 = (2 * p) >> 4;
            XsP[hb_word(kt2 * 16 + ((l0 + 0) >> 3), kk, (l0 + 0) & 7)] = f2h2(A.x, B.x);
            XsP[hb_word(kt2 * 16 + ((l0 + 1) >> 3), kk, (l0 + 1) & 7)] = f2h2(A.y, B.y);
            XsP[hb_word(kt2 * 16 + ((l0 + 2) >> 3), kk, (l0 + 2) & 7)] = f2h2(A.z, B.z);
            XsP[hb_word(kt2 * 16 + ((l0 + 3) >> 3), kk, (l0 + 3) & 7)] = f2h2(A.w, B.w);
        }
        __syncthreads();

        #pragma unroll
        for (int ks = 0; ks < 2; ks++) {
            uint32_t a[2][4];
            a_frag16(a[0], WsP, (wm * 2 + 0) * 2 + ks, g, tig);
            a_frag16(a[1], WsP, (wm * 2 + 1) * 2 + ks, g, tig);
            #pragma unroll
            for (int nt = 0; nt < 8; nt++) {
                uint32_t bf[2];
                b_frag16(bf, XsP, ks * 16 + wn * 8 + nt, g, tig);
                mma16(acc[nt], a[0], bf);
                mma16(acc[8 + nt], a[1], bf);
            }
        }
    }

    #pragma unroll
    for (int mt = 0; mt < 2; mt++) {
        #pragma unroll
        for (int nt = 0; nt < 8; nt++) {
            #pragma unroll
            for (int reg = 0; reg < 4; reg++) {
                const int m = bm * 128 + wm * 32 + mt * 16 + g + ((reg >= 2) ? 8 : 0);
                const int l = ltile + wn * 64 + nt * 8 + tig * 2 + (reg & 1);
                out[((size_t)b * DIM + m) * Ln + l] = acc[mt * 8 + nt][reg] + bias[m];
            }
        }
    }
}

// ---------------------------------------------------------------------------
extern "C" void kernel_launch(void* const* d_in, const int* in_sizes, int n_in,
                              void* d_out, int out_size) {
    const float* x     = (const float*)d_in[0];
    const float* w_qkv = (const float*)d_in[1];
    const float* w_out = (const float*)d_in[2];
    const float* b_out = (const float*)d_in[3];
    float* out = (float*)d_out;

    cudaFuncSetAttribute(attn_mma, cudaFuncAttributeMaxDynamicSharedMemorySize, ATTN_SMEM);

    qkv_mma<<<dim3(Ln / 128, (3 * HID) / 128, Bn), 256>>>(x, w_qkv);
    attn_mma<<<dim3(Ln / 128, Bn * Hn), 256, ATTN_SMEM>>>();
    outp_mma<<<dim3(Ln / 128, HID / 128, Bn), 256>>>(w_out, b_out, out);
}